// round 16
// baseline (speedup 1.0000x reference)
#include <cuda_runtime.h>
#include <math.h>
#include <float.h>

// ---------------- problem constants ----------------
#define NB_    8
#define TT_    497
#define LAUD_  32000
#define HOP_   64
#define NFFT_  256
#define AE_    256
#define BTL_   256
#define HH_    512
#define FC_    385
#define FCP_   400        // padded stride for xc (K=385 -> 25*16)
#define NFREQ_ 129
#define EMBD_  20
#define NBLK_  32
#define NPAIR_ 15
#define KPACK_ 514
#define KPACKP_ 528       // padded stride for rows (33*16)
#define ECSN_  528        // fused enc+spec row: [0,256) enc, [256,385) Re, [392,521) Im
#define RE0_   256
#define IM0_   392
#define ANS_   64
#define TCNB_  148        // persistent TCN grid (<= SM count, 1 block/SM resident)
#define DWCH_  (MROWS_*HH_/1024)  // dwconv chunks (1988)
#define MROWS_ (NB_*TT_)          // 3976
#define MROWS2_ (NB_*2*TT_)       // 7952
#define NSEP_  (FC_*EMBD_)        // 7700

// ---------------- device scratch ----------------
__device__ float g_frames[MROWS_*NFFT_];
__device__ float g_ecs[(long)MROWS_*ECSN_];
__device__ float g_xc[MROWS_*FCP_];
__device__ float g_x[MROWS_*BTL_];
__device__ float g_y1[MROWS_*HH_];
__device__ float g_y2[MROWS_*HH_];
__device__ float g_emb[(long)MROWS_*NSEP_];
__device__ float g_rows[(long)MROWS2_*KPACKP_];
__device__ float g_tot[MROWS2_*NFFT_];
__device__ double g_dstat[NBLK_*2*16];
__device__ float g_apart[NB_*NPAIR_*ANS_*42];
__device__ float g_attrAll[NB_*NPAIR_*40];
__device__ float g_sp01[NB_*NPAIR_];
__device__ float g_att[NB_*40];
__device__ float g_c256[256], g_s256[256], g_win[256], g_invwin[256];
__device__ float g_Bpack[KPACK_*256], g_biasPack[256];
__device__ float g_ECS[NFFT_*ECSN_];
__device__ float g_ecsb[ECSN_];
__device__ float g_Wg[NBLK_*HH_*BTL_];
__device__ float g_u[NBLK_*BTL_], g_v[NBLK_*BTL_];
__device__ unsigned g_barCount, g_barGen;

__constant__ int d_combs[NPAIR_][2] = {
  {0,1},{0,2},{0,3},{0,4},{0,5},{1,2},{1,3},{1,4},{1,5},
  {2,3},{2,4},{2,5},{3,4},{3,5},{4,5}
};

// ---------------- smem pool shared by gemm/dwconv bodies ----------------
struct SmemPool {
  float As[2][64][16];     // col k ^ (4*((m>>1)&3))
  float Bs[2][16][128];    // col n ^ (8*(k&3))
  float s_m[8], s_i[8];
  double wred[8][4];
  double wredH[8][2];
};

// ---------------- software grid barrier (all TCNB_ blocks resident) ----------------
__device__ __forceinline__ void grid_bar() {
  __threadfence();
  __syncthreads();
  if (threadIdx.x == 0) {
    unsigned gen = *((volatile unsigned*)&g_barGen);
    unsigned t = atomicAdd(&g_barCount, 1u);
    if (t == TCNB_ - 1) {
      *((volatile unsigned*)&g_barCount) = 0u;
      __threadfence();
      atomicAdd(&g_barGen, 1u);
    } else {
      while (*((volatile unsigned*)&g_barGen) == gen) { }
    }
    __threadfence();
  }
  __syncthreads();
}

// ---------------- tables (also zeroes stat accumulators + barrier) ----------------
__global__ void init_tables_k(float* c, float* s, float* win, float* invwin,
                              double* dstat) {
  int n = threadIdx.x;
  double a = 2.0 * 3.14159265358979323846 * (double)n / 256.0;
  double cv = cos(a), sv = sin(a);
  c[n] = (float)cv; s[n] = (float)sv;
  float w = (float)sqrt(0.5 - 0.5 * cv);
  win[n] = w;
  #pragma unroll
  for (int q = 0; q < 4; q++) dstat[n + q*256] = 0.0;
  if (n == 0) { g_barCount = 0u; g_barGen = 0u; }
  __syncthreads();
  __shared__ float dn[64];
  if (n < 64) {
    float d = 0.f;
    for (int q = 0; q < 4; q++) { float wv = win[n + 64*q]; d += wv*wv; }
    dn[n] = d;
  }
  __syncthreads();
  invwin[n] = win[n] / dn[n & 63];
}

// fused encoder + windowed-DFT matrix
__global__ void ecs_k(const float* __restrict__ enc_w, const float* __restrict__ enc_b,
                      const float* __restrict__ c, const float* __restrict__ s,
                      const float* __restrict__ win,
                      float* __restrict__ ECS, float* __restrict__ ecsb) {
  int j = blockIdx.x, n = threadIdx.x;
  float v;
  if (j < 256) v = enc_w[n*256 + j];
  else {
    int jj = j - RE0_;
    if (jj < NFREQ_) v = win[n] * c[(n * jj) & 255];
    else if (j >= IM0_ && j < IM0_ + NFREQ_) v = -win[n] * s[(n * (j - IM0_)) & 255];
    else v = 0.f;
  }
  ECS[n * ECSN_ + j] = v;
  if (n == 0) ecsb[j] = (j < 256) ? enc_b[j] : 0.f;
}

__global__ void pack_k(const float* __restrict__ dec_w, const float* __restrict__ dec_b,
                       const float* __restrict__ c, const float* __restrict__ s,
                       const float* __restrict__ invwin,
                       float* __restrict__ Bp, float* __restrict__ biasP) {
  int k = blockIdx.x, n = threadIdx.x;
  float v;
  if (k < 256) {
    v = 0.5f * dec_w[k*256 + n];
  } else if (k < 385) {
    int j = k - 256;
    float wj = (j == 0 || j == 128) ? 1.f : 2.f;
    int m = (j * n) & 255;
    v = 0.5f * invwin[n] * wj * c[m] * (1.f/256.f);
  } else {
    int j = k - 385;
    float wj = (j == 0 || j == 128) ? 1.f : 2.f;
    int m = (j * n) & 255;
    v = -0.5f * invwin[n] * wj * s[m] * (1.f/256.f);
  }
  Bp[k*256 + n] = v;
  if (k == 0) biasP[n] = 0.5f * dec_b[n];
}

__global__ void prep_wg_k(const float* __restrict__ c2w, const float* __restrict__ g2g,
                          float* __restrict__ Wg) {
  long idx = (long)blockIdx.x * 256 + threadIdx.x;
  int i = (int)(idx / (HH_*BTL_/4));
  int rem = (int)(idx % (HH_*BTL_/4));
  int k = rem / (BTL_/4);
  float gv = g2g[i*HH_ + k];
  float4 w = ((const float4*)c2w)[idx];
  w.x *= gv; w.y *= gv; w.z *= gv; w.w *= gv;
  ((float4*)Wg)[idx] = w;
}

__global__ __launch_bounds__(512)
void prep_uv_k(const float* __restrict__ c2w, const float* __restrict__ g2g,
               const float* __restrict__ g2b,
               float* __restrict__ u, float* __restrict__ v) {
  int i = blockIdx.x;
  int l = threadIdx.x & 127;
  int n = blockIdx.y * 128 + l;
  int ks = threadIdx.x >> 7;
  const float* W  = c2w + (long)i*HH_*BTL_ + n;
  const float* gg = g2g + i*HH_;
  const float* bb = g2b + i*HH_;
  float au = 0.f, av = 0.f;
  int k0 = ks * 128;
  #pragma unroll 4
  for (int k = k0; k < k0 + 128; k++) {
    float w = W[(long)k*BTL_];
    au = fmaf(bb[k], w, au);
    av = fmaf(gg[k], w, av);
  }
  __shared__ float su[4][128], sv[4][128];
  su[ks][l] = au; sv[ks][l] = av;
  __syncthreads();
  if (ks == 0) {
    u[i*BTL_ + n] = (su[0][l] + su[1][l]) + (su[2][l] + su[3][l]);
    v[i*BTL_ + n] = (sv[0][l] + sv[1][l]) + (sv[2][l] + sv[3][l]);
  }
}

// ---------------- framing ----------------
__global__ void frames_k(const float* __restrict__ aud, float* __restrict__ frames) {
  int bt = blockIdx.x, n = threadIdx.x;
  int b = bt / TT_, t = bt % TT_;
  int off = b * 2 * LAUD_ + t * HOP_ + n;
  frames[bt * NFFT_ + n] = aud[off] + aud[off + LAUD_];
}

// ---------------- cLN (reads fused ecs buffer) ----------------
__global__ void cln_k(const float* __restrict__ ecs,
                      const float* __restrict__ gamma, const float* __restrict__ beta,
                      float* __restrict__ xc) {
  int bt = blockIdx.x, tid = threadIdx.x;
  const float* row = ecs + (long)bt * ECSN_;
  __shared__ float vals[FC_];
  for (int f = tid; f < FC_; f += 128) {
    if (f < AE_) vals[f] = row[f];
    else {
      int j = f - AE_;
      float re = row[RE0_ + j];
      float im = row[IM0_ + j];
      vals[f] = log1pf(sqrtf(re*re + im*im));
    }
  }
  __syncthreads();
  double s = 0.0, ss = 0.0;
  for (int f = tid; f < FC_; f += 128) { double v = vals[f]; s += v; ss += v*v; }
  __shared__ double rs[128], rss[128];
  rs[tid] = s; rss[tid] = ss; __syncthreads();
  for (int o = 64; o > 0; o >>= 1) {
    if (tid < o) { rs[tid] += rs[tid+o]; rss[tid] += rss[tid+o]; }
    __syncthreads();
  }
  __shared__ float mS, iS;
  if (tid == 0) {
    double m = rs[0] / FC_;
    double var = rss[0] / FC_ - m*m;
    mS = (float)m; iS = (float)rsqrt(var + 1e-12);
  }
  __syncthreads();
  for (int f = tid; f < FC_; f += 128)
    xc[bt*FCP_ + f] = (vals[f] - mS) * iS * gamma[f] + beta[f];
  for (int f = FC_ + tid; f < FCP_; f += 128)
    xc[bt*FCP_ + f] = 0.f;
}

// ---------------- tf32 helpers ----------------
__device__ __forceinline__ void split_tf32(float x, unsigned& h, unsigned& l) {
  asm("cvt.rna.tf32.f32 %0, %1;" : "=r"(h) : "f"(x));
  float r = x - __uint_as_float(h);
  asm("cvt.rna.tf32.f32 %0, %1;" : "=r"(l) : "f"(r));
}

__device__ __forceinline__ void mma8(float* c, const unsigned* a, const unsigned* b) {
  asm volatile(
    "mma.sync.aligned.m16n8k8.row.col.f32.tf32.tf32.f32 "
    "{%0,%1,%2,%3}, {%4,%5,%6,%7}, {%8,%9}, {%0,%1,%2,%3};\n"
    : "+f"(c[0]), "+f"(c[1]), "+f"(c[2]), "+f"(c[3])
    : "r"(a[0]), "r"(a[1]), "r"(a[2]), "r"(a[3]), "r"(b[0]), "r"(b[1]));
}

__device__ __forceinline__ float wsum(float x) {
  #pragma unroll
  for (int o = 16; o > 0; o >>= 1) x += __shfl_down_sync(0xffffffffu, x, o);
  return x;
}

// ---------------- GEMM body (device; CG = use L2-only ld/st for A and C) ------
// Block tile 64x128x16, 256 threads = 8 warps (2M x 4N), warp tile 32x32.
// Raw fp32 in XOR-swizzled smem; split to tf32 hi/lo at fragment-load time;
// 3xTF32 compensation. EPI: 0 none, 1 relu, 2 prelu, 3 residual+gLN affine,
// 4 relu-on-cols<256. STAT: fused per-batch (sum,sumsq) into dstat.
template<int EPI, bool STAT, bool CG>
__device__ __forceinline__
void gemm_body(SmemPool& sp, int bxi, int byi,
               const float* __restrict__ A, const float* __restrict__ Bm,
               const float* __restrict__ bias, float* __restrict__ C,
               int M, int N, int K, int lda,
               const float* __restrict__ prelu,
               const float* __restrict__ uvec, const float* __restrict__ vvec,
               const double* __restrict__ part, double* __restrict__ dstat) {
  constexpr int BM = 64, BK = 16;
  const int tid = threadIdx.x;
  if (EPI == 3 && tid < 8) {
    const double pb = (double)(TT_*HH_);
    double mm = part[tid*2] / pb;
    sp.s_m[tid] = (float)mm;
    sp.s_i[tid] = (float)rsqrt(part[tid*2+1] / pb - mm*mm + 1e-12);
  }

  const int row0 = byi * BM, col0 = bxi * 128;
  const int wid = tid >> 5, lane = tid & 31;
  const int g = lane >> 2, t = lane & 3;
  const int m0w = (wid >> 2) * 32;
  const int n0w = (wid & 3) * 32;

  float acc[2][4][4];
  #pragma unroll
  for (int i = 0; i < 2; i++)
    #pragma unroll
    for (int j = 0; j < 4; j++)
      #pragma unroll
      for (int q = 0; q < 4; q++) acc[i][j][q] = 0.f;

  float4 aR, bR[2];
  const int am = tid >> 2, ak4 = (tid & 3) << 2;
  const int asw = ak4 ^ (4 * ((am >> 1) & 3));

  auto loadA = [&](int kt) {
    int row = row0 + am, gk = kt * BK + ak4;
    float4 r = make_float4(0.f, 0.f, 0.f, 0.f);
    if (row < M) {
      const float4* p = (const float4*)(A + (long)row * lda + gk);
      r = CG ? __ldcg(p) : *p;
    }
    aR = r;
  };
  auto loadB = [&](int kt) {
    #pragma unroll
    for (int p = 0; p < 2; p++) {
      int idx = tid + p * 256;
      int bk = idx >> 5, bn4 = (idx & 31) << 2;
      int gk = kt * BK + bk, col = col0 + bn4;
      float4 r = make_float4(0.f, 0.f, 0.f, 0.f);
      if (gk < K) {
        const float* bp = Bm + (long)gk * N + col;
        if (col + 3 < N) r = *(const float4*)bp;
        else {
          if (col     < N) r.x = bp[0];
          if (col + 1 < N) r.y = bp[1];
          if (col + 2 < N) r.z = bp[2];
        }
      }
      bR[p] = r;
    }
  };
  auto storeT = [&](int buf) {
    *(float4*)&sp.As[buf][am][asw] = aR;
    #pragma unroll
    for (int p = 0; p < 2; p++) {
      int idx = tid + p * 256;
      int bk = idx >> 5, bn4 = (idx & 31) << 2;
      *(float4*)&sp.Bs[buf][bk][bn4 ^ (8 * (bk & 3))] = bR[p];
    }
  };

  const int ktot = (K + BK - 1) / BK;
  loadA(0); loadB(0);
  storeT(0);
  __syncthreads();

  for (int kt = 0; kt < ktot; kt++) {
    const int buf = kt & 1;
    const bool more = (kt + 1 < ktot);
    if (more) { loadA(kt + 1); loadB(kt + 1); }

    #pragma unroll
    for (int ks = 0; ks < 2; ks++) {
      const int k1 = ks * 8 + t, k2 = k1 + 4;
      unsigned ah[2][4], al[2][4];
      #pragma unroll
      for (int mi = 0; mi < 2; mi++) {
        int rA = m0w + mi * 16 + g;
        int sw = 4 * ((rA >> 1) & 3);
        float r0 = sp.As[buf][rA    ][k1 ^ sw];
        float r1 = sp.As[buf][rA + 8][k1 ^ sw];
        float r2 = sp.As[buf][rA    ][k2 ^ sw];
        float r3 = sp.As[buf][rA + 8][k2 ^ sw];
        split_tf32(r0, ah[mi][0], al[mi][0]);
        split_tf32(r1, ah[mi][1], al[mi][1]);
        split_tf32(r2, ah[mi][2], al[mi][2]);
        split_tf32(r3, ah[mi][3], al[mi][3]);
      }
      unsigned bh[4][2], bl[4][2];
      const int bsw = 8 * (k1 & 3);
      #pragma unroll
      for (int ni = 0; ni < 4; ni++) {
        int cn = (n0w + ni * 8 + g) ^ bsw;
        float r0 = sp.Bs[buf][k1][cn];
        float r1 = sp.Bs[buf][k2][cn];
        split_tf32(r0, bh[ni][0], bl[ni][0]);
        split_tf32(r1, bh[ni][1], bl[ni][1]);
      }
      #pragma unroll
      for (int mi = 0; mi < 2; mi++)
        #pragma unroll
        for (int ni = 0; ni < 4; ni++) {
          mma8(acc[mi][ni], ah[mi], bl[ni]);
          mma8(acc[mi][ni], al[mi], bh[ni]);
          mma8(acc[mi][ni], ah[mi], bh[ni]);
        }
    }

    if (more) { storeT(buf ^ 1); __syncthreads(); }
  }

  // epilogue
  const int bLo = row0 / TT_;
  const int rsplit = (bLo + 1) * TT_;
  float sLo = 0.f, qLo = 0.f, sHi = 0.f, qHi = 0.f;
  #pragma unroll
  for (int mi = 0; mi < 2; mi++) {
    #pragma unroll
    for (int ii = 0; ii < 2; ii++) {
      int row = row0 + m0w + mi * 16 + g + ii * 8;
      if (row >= M) continue;
      float si = 1.f, smn = 0.f;
      if (EPI == 3) { int b = row / TT_; si = sp.s_i[b]; smn = sp.s_m[b]; }
      float* crow = C + (long)row * N;
      float rs = 0.f, rq = 0.f;
      #pragma unroll
      for (int ni = 0; ni < 4; ni++) {
        #pragma unroll
        for (int jj = 0; jj < 2; jj++) {
          int cc = col0 + n0w + ni * 8 + 2 * t + jj;
          if (cc >= N) continue;
          float vx = acc[mi][ni][ii * 2 + jj];
          if (EPI == 0) vx += bias[cc];
          if (EPI == 1) { vx += bias[cc]; vx = fmaxf(vx, 0.f); }
          if (EPI == 2) { vx += bias[cc]; vx = fmaxf(vx, 0.f) + prelu[cc] * fminf(vx, 0.f); }
          if (EPI == 3) {
            float prev = CG ? __ldcg(&crow[cc]) : crow[cc];
            vx = prev + si * vx + (uvec[cc] - smn * si * vvec[cc]) + bias[cc];
          }
          if (EPI == 4) { vx += bias[cc]; if (cc < 256) vx = fmaxf(vx, 0.f); }
          if (CG) __stcg(&crow[cc], vx); else crow[cc] = vx;
          if (STAT) { rs += vx; rq = fmaf(vx, vx, rq); }
        }
      }
      if (STAT) {
        if (row < rsplit) { sLo += rs; qLo += rq; }
        else              { sHi += rs; qHi += rq; }
      }
    }
  }
  if (STAT) {
    sLo = wsum(sLo); qLo = wsum(qLo); sHi = wsum(sHi); qHi = wsum(qHi);
    if (lane == 0) {
      sp.wred[wid][0] = sLo; sp.wred[wid][1] = qLo;
      sp.wred[wid][2] = sHi; sp.wred[wid][3] = qHi;
    }
    __syncthreads();
    if (tid < 4) {
      double a = 0.0;
      #pragma unroll
      for (int w = 0; w < 8; w++) a += sp.wred[w][tid];
      int b = (tid < 2) ? bLo : bLo + 1;
      if (b < NB_ && a != 0.0) atomicAdd(&dstat[b*2 + (tid & 1)], a);
    }
  }
  __syncthreads();   // protect smem reuse across tile-loop iterations
}

// standalone GEMM wrapper (plain caching; separate launches)
template<int EPI, bool STAT>
__global__ __launch_bounds__(256)
void gemmT(const float* __restrict__ A, const float* __restrict__ Bm,
           const float* __restrict__ bias, float* __restrict__ C,
           int M, int N, int K, int lda,
           const float* __restrict__ prelu,
           const float* __restrict__ uvec, const float* __restrict__ vvec,
           const double* __restrict__ part, double* __restrict__ dstat) {
  __shared__ SmemPool sp;
  gemm_body<EPI, STAT, false>(sp, blockIdx.x, blockIdx.y, A, Bm, bias, C,
                              M, N, K, lda, prelu, uvec, vvec, part, dstat);
}

// ---------------- dwconv body (persistent; L2-only data accesses) ----------------
__device__ __forceinline__
void dw_setup(SmemPool& sp, const double* __restrict__ partA) {
  int tid = threadIdx.x;
  if (tid < 8) {
    const double pb = (double)(TT_*HH_);
    double mm = partA[tid*2] / pb;
    sp.s_m[tid] = (float)mm;
    sp.s_i[tid] = (float)rsqrt(partA[tid*2+1] / pb - mm*mm + 1e-12);
  }
  __syncthreads();
}

__device__ __forceinline__
void dw_body(SmemPool& sp, int c,
             const float* __restrict__ y1, float* __restrict__ y2,
             const float* __restrict__ w, double* __restrict__ dstatB,
             const float* __restrict__ g, const float* __restrict__ be,
             const float* __restrict__ p2, int d) {
  int tid = threadIdx.x;
  int idx4 = c * 256 + tid;
  int c4 = (idx4 & 127) << 2;
  int bt = idx4 >> 7;
  int t = bt % TT_, b = bt / TT_;
  float m = sp.s_m[b], si = sp.s_i[b];
  float4 gg = *(const float4*)(g + c4);
  float4 bb = *(const float4*)(be + c4);
  float4 pp = *(const float4*)(p2 + c4);
  float4 acc = make_float4(0.f,0.f,0.f,0.f);
  #pragma unroll
  for (int k = 0; k < 3; k++) {
    int tt = t + (k - 1) * d;
    if (tt >= 0 && tt < TT_) {
      float4 v = __ldcg((const float4*)(y1 + ((long)(b*TT_ + tt))*HH_ + c4));
      float4 wv = *(const float4*)(w + k*HH_ + c4);
      acc.x = fmaf(wv.x, (v.x - m)*si*gg.x + bb.x, acc.x);
      acc.y = fmaf(wv.y, (v.y - m)*si*gg.y + bb.y, acc.y);
      acc.z = fmaf(wv.z, (v.z - m)*si*gg.z + bb.z, acc.z);
      acc.w = fmaf(wv.w, (v.w - m)*si*gg.w + bb.w, acc.w);
    }
  }
  float4 o;
  o.x = fmaxf(acc.x, 0.f) + pp.x * fminf(acc.x, 0.f);
  o.y = fmaxf(acc.y, 0.f) + pp.y * fminf(acc.y, 0.f);
  o.z = fmaxf(acc.z, 0.f) + pp.z * fminf(acc.z, 0.f);
  o.w = fmaxf(acc.w, 0.f) + pp.w * fminf(acc.w, 0.f);
  __stcg((float4*)(y2 + (long)idx4*4), o);

  const int bLo = (c * 2) / TT_;
  float s = o.x + o.y + o.z + o.w;
  float q = o.x*o.x + o.y*o.y + o.z*o.z + o.w*o.w;
  float sLo = (b == bLo) ? s : 0.f, qLo = (b == bLo) ? q : 0.f;
  float sHi = (b == bLo) ? 0.f : s, qHi = (b == bLo) ? 0.f : q;
  sLo = wsum(sLo); qLo = wsum(qLo); sHi = wsum(sHi); qHi = wsum(qHi);
  int lane = tid & 31, wid = tid >> 5;
  if (lane == 0) {
    sp.wred[wid][0] = sLo; sp.wred[wid][1] = qLo;
    sp.wredH[wid][0] = sHi; sp.wredH[wid][1] = qHi;
  }
  __syncthreads();
  if (tid < 2) {
    double a = 0.0, ah = 0.0;
    #pragma unroll
    for (int w2 = 0; w2 < 8; w2++) { a += sp.wred[w2][tid]; ah += sp.wredH[w2][tid]; }
    if (a  != 0.0) atomicAdd(&dstatB[bLo*2 + tid], a);
    int bH = bLo + 1;
    if (bH < NB_ && ah != 0.0) atomicAdd(&dstatB[bH*2 + tid], ah);
  }
  __syncthreads();
}

// ---------------- persistent TCN kernel (all 32 blocks, 3 phases each) ---------
__global__ __launch_bounds__(256)
void tcn_k(float* __restrict__ x, float* __restrict__ y1, float* __restrict__ y2,
           const float* __restrict__ c1w, const float* __restrict__ c1b,
           const float* __restrict__ p1,
           const float* __restrict__ dwv, const float* __restrict__ g1g,
           const float* __restrict__ g1b, const float* __restrict__ p2,
           const float* __restrict__ Wg, const float* __restrict__ c2b,
           const float* __restrict__ uv, const float* __restrict__ vv,
           double* __restrict__ dstat) {
  __shared__ SmemPool sp;
  for (int i = 0; i < NBLK_; i++) {
    int di = 1 << (i & 7);
    double* dA = dstat + (2*i) * 16;
    double* dB = dstat + (2*i + 1) * 16;
    // phase 1: c1 GEMM (N=512 -> 4x63 = 252 tiles) + prelu + y1 stats
    for (int tile = blockIdx.x; tile < 252; tile += TCNB_)
      gemm_body<2,true,true>(sp, tile & 3, tile >> 2,
                             x, c1w + (long)i*BTL_*HH_, c1b + i*HH_, y1,
                             MROWS_, 512, 256, 256, p1 + i*HH_,
                             nullptr, nullptr, nullptr, dA);
    grid_bar();
    // phase 2: gLN1 finalize + dwconv + prelu2 + y2 stats
    dw_setup(sp, dA);
    for (int c = blockIdx.x; c < DWCH_; c += TCNB_)
      dw_body(sp, c, y1, y2, dwv + i*3*HH_, dB,
              g1g + i*HH_, g1b + i*HH_, p2 + i*HH_, di);
    grid_bar();
    // phase 3: c2 GEMM (N=256 -> 2x63 = 126 tiles) + gLN2 affine + residual
    for (int tile = blockIdx.x; tile < 126; tile += TCNB_)
      gemm_body<3,false,true>(sp, tile & 1, tile >> 1,
                              y2, Wg + (long)i*HH_*BTL_, c2b + i*BTL_, x,
                              MROWS_, 256, 512, 512, nullptr,
                              uv + i*BTL_, vv + i*BTL_, dB, nullptr);
    grid_bar();
  }
}

// ---------------- attractor ----------------
__global__ __launch_bounds__(128)
void attr_part_k(const float* __restrict__ emb, const float* __restrict__ anchors,
                 float* __restrict__ part) {
  int bp = blockIdx.x % (NB_*NPAIR_);
  int s  = blockIdx.x / (NB_*NPAIR_);
  int b = bp / NPAIR_, p = bp % NPAIR_;
  int tid = threadIdx.x;
  __shared__ float a0[EMBD_], a1[EMBD_];
  if (tid < EMBD_) {
    a0[tid] = anchors[d_combs[p][0] * EMBD_ + tid];
    a1[tid] = anchors[d_combs[p][1] * EMBD_ + tid];
  }
  __syncthreads();
  const int rows = TT_ * FC_;
  int chunk = (rows + ANS_ - 1) / ANS_;
  int st = s * chunk, en = min(rows, st + chunk);
  float num0[EMBD_], sev[EMBD_];
  #pragma unroll
  for (int i = 0; i < EMBD_; i++) { num0[i] = 0.f; sev[i] = 0.f; }
  float den0 = 0.f;
  const float* base = emb + (long)b * rows * EMBD_;
  for (int r = st + tid; r < en; r += 128) {
    const float4* e4 = (const float4*)(base + (long)r * EMBD_);
    float ev[EMBD_];
    #pragma unroll
    for (int q = 0; q < 5; q++) {
      float4 v = e4[q];
      ev[q*4+0] = v.x; ev[q*4+1] = v.y; ev[q*4+2] = v.z; ev[q*4+3] = v.w;
    }
    float dd0 = 0.f, dd1 = 0.f;
    #pragma unroll
    for (int i = 0; i < EMBD_; i++) { dd0 = fmaf(ev[i], a0[i], dd0); dd1 = fmaf(ev[i], a1[i], dd1); }
    float s0 = 1.f / (1.f + expf(dd1 - dd0));
    den0 += s0;
    #pragma unroll
    for (int i = 0; i < EMBD_; i++) { num0[i] = fmaf(s0, ev[i], num0[i]); sev[i] += ev[i]; }
  }
  __shared__ float red[4][41];
  int lane = tid & 31, w = tid >> 5;
  den0 = wsum(den0);
  #pragma unroll
  for (int i = 0; i < EMBD_; i++) { num0[i] = wsum(num0[i]); sev[i] = wsum(sev[i]); }
  if (lane == 0) {
    red[w][0] = den0;
    #pragma unroll
    for (int i = 0; i < EMBD_; i++) { red[w][1+i] = num0[i]; red[w][21+i] = sev[i]; }
  }
  __syncthreads();
  if (tid < 41) {
    float a = red[0][tid] + red[1][tid] + red[2][tid] + red[3][tid];
    part[(bp * ANS_ + s) * 42 + tid] = a;
  }
}

__global__ void attr_comb_k(const float* __restrict__ part, float* __restrict__ attrAll,
                            float* __restrict__ sp01) {
  int bp = blockIdx.x, tid = threadIdx.x;
  __shared__ float comb[41];
  if (tid < 41) {
    double a = 0.0;
    for (int s = 0; s < ANS_; s++) a += part[(bp * ANS_ + s) * 42 + tid];
    comb[tid] = (float)a;
  }
  __syncthreads();
  __shared__ float at[40];
  if (tid < 40) {
    int c = tid / EMBD_, e = tid % EMBD_;
    float den0 = comb[0];
    float den1 = (float)(TT_ * FC_) - den0;
    float val;
    if (c == 0) val = comb[1 + e] / den0;
    else        val = (comb[21 + e] - comb[1 + e]) / den1;
    at[tid] = val;
    attrAll[bp * 40 + tid] = val;
  }
  __syncthreads();
  if (tid == 0) {
    float s = 0.f;
    for (int e = 0; e < EMBD_; e++) s += at[e] * at[EMBD_ + e];
    sp01[bp] = s;
  }
}

__global__ void choose_k(const float* __restrict__ sp01, const float* __restrict__ attrAll,
                         float* __restrict__ attract) {
  int b = threadIdx.x;
  if (b >= NB_) return;
  float best = sp01[b * NPAIR_];
  int bi = 0;
  for (int p = 1; p < NPAIR_; p++) {
    float v = sp01[b * NPAIR_ + p];
    if (v < best) { best = v; bi = p; }
  }
  for (int k = 0; k < 40; k++)
    attract[b * 40 + k] = attrAll[(b * NPAIR_ + bi) * 40 + k];
}

// ---------------- code rows ----------------
__global__ __launch_bounds__(128)
void code_k(const float* __restrict__ emb, const float* __restrict__ attract,
            const float* __restrict__ ecs, float* __restrict__ rows) {
  int bt = blockIdx.x, tid = threadIdx.x;
  int b = bt / TT_, t = bt % TT_;
  __shared__ float at[40];
  if (tid < 40) at[tid] = attract[b * 40 + tid];
  __syncthreads();
  const float* erow = ecs + (long)bt * ECSN_;
  long r0 = ((long)(b * 2 + 0) * TT_ + t) * KPACKP_;
  long r1 = ((long)(b * 2 + 1) * TT_ + t) * KPACKP_;
  for (int f = tid; f < FC_; f += 128) {
    const float4* e4 = (const float4*)(emb + ((long)bt * FC_ + f) * EMBD_);
    float l0 = 0.f, l1 = 0.f;
    #pragma unroll
    for (int q = 0; q < 5; q++) {
      float4 v = e4[q];
      l0 = fmaf(v.x, at[q*4+0], l0); l0 = fmaf(v.y, at[q*4+1], l0);
      l0 = fmaf(v.z, at[q*4+2], l0); l0 = fmaf(v.w, at[q*4+3], l0);
      l1 = fmaf(v.x, at[20+q*4+0], l1); l1 = fmaf(v.y, at[20+q*4+1], l1);
      l1 = fmaf(v.z, at[20+q*4+2], l1); l1 = fmaf(v.w, at[20+q*4+3], l1);
    }
    if (f < AE_) {
      float fe = erow[f];
      rows[r0 + f] = l0 * fe;
      rows[r1 + f] = l1 * fe;
    } else {
      int j = f - AE_;
      float re = erow[RE0_ + j];
      float im = erow[IM0_ + j];
      rows[r0 + 256 + j] = l0 * re;
      rows[r0 + 385 + j] = l0 * im;
      rows[r1 + 256 + j] = l1 * re;
      rows[r1 + 385 + j] = l1 * im;
    }
  }
  if (tid < KPACKP_ - KPACK_) {
    rows[r0 + KPACK_ + tid] = 0.f;
    rows[r1 + KPACK_ + tid] = 0.f;
  }
}

// ---------------- overlap-add ----------------
__global__ void ola_k(const float* __restrict__ tot, float* __restrict__ out) {
  int idx = blockIdx.x * blockDim.x + threadIdx.x;
  if (idx >= NB_ * 2 * LAUD_) return;
  int l = idx % LAUD_;
  int bc = idx / LAUD_;
  int tlo = (l >= NFFT_) ? ((l - NFFT_) >> 6) + 1 : 0;
  int thi = min(TT_ - 1, l >> 6);
  float acc = 0.f;
  for (int t = tlo; t <= thi; t++)
    acc += tot[((long)bc * TT_ + t) * NFFT_ + (l - (t << 6))];
  out[idx] = acc;
}

// ---------------- host orchestration ----------------
extern "C" void kernel_launch(void* const* d_in, const int* in_sizes, int n_in,
                              void* d_out, int out_size) {
  const float* audios = (const float*)d_in[0];
  const float* enc_w  = (const float*)d_in[1];
  const float* enc_b  = (const float*)d_in[2];
  const float* bgam   = (const float*)d_in[3];
  const float* bbet   = (const float*)d_in[4];
  const float* bw     = (const float*)d_in[5];
  const float* bbi    = (const float*)d_in[6];
  const float* c1w    = (const float*)d_in[7];
  const float* c1b    = (const float*)d_in[8];
  const float* p1     = (const float*)d_in[9];
  const float* g1g    = (const float*)d_in[10];
  const float* g1b    = (const float*)d_in[11];
  const float* dwv    = (const float*)d_in[12];
  const float* p2     = (const float*)d_in[13];
  const float* g2g    = (const float*)d_in[14];
  const float* g2b    = (const float*)d_in[15];
  const float* c2w    = (const float*)d_in[16];
  const float* c2b    = (const float*)d_in[17];
  const float* sw     = (const float*)d_in[18];
  const float* sb     = (const float*)d_in[19];
  const float* anchors= (const float*)d_in[20];
  const float* dec_w  = (const float*)d_in[21];
  const float* dec_b  = (const float*)d_in[22];
  float* out = (float*)d_out;

  float *frames,*ecs,*xc,*x,*y1,*y2,*emb,*rows,*tot;
  float *apart,*attrAll,*sp01,*attv;
  float *c256,*s256,*win,*invwin,*Bpack,*biasPack,*ECS,*ecsb,*Wg,*uv,*vv;
  double *dstat;
  cudaGetSymbolAddress((void**)&frames, g_frames);
  cudaGetSymbolAddress((void**)&ecs,    g_ecs);
  cudaGetSymbolAddress((void**)&xc,     g_xc);
  cudaGetSymbolAddress((void**)&x,      g_x);
  cudaGetSymbolAddress((void**)&y1,     g_y1);
  cudaGetSymbolAddress((void**)&y2,     g_y2);
  cudaGetSymbolAddress((void**)&emb,    g_emb);
  cudaGetSymbolAddress((void**)&rows,   g_rows);
  cudaGetSymbolAddress((void**)&tot,    g_tot);
  cudaGetSymbolAddress((void**)&dstat,  g_dstat);
  cudaGetSymbolAddress((void**)&apart,  g_apart);
  cudaGetSymbolAddress((void**)&attrAll,g_attrAll);
  cudaGetSymbolAddress((void**)&sp01,   g_sp01);
  cudaGetSymbolAddress((void**)&attv,   g_att);
  cudaGetSymbolAddress((void**)&c256,   g_c256);
  cudaGetSymbolAddress((void**)&s256,   g_s256);
  cudaGetSymbolAddress((void**)&win,    g_win);
  cudaGetSymbolAddress((void**)&invwin, g_invwin);
  cudaGetSymbolAddress((void**)&Bpack,  g_Bpack);
  cudaGetSymbolAddress((void**)&biasPack, g_biasPack);
  cudaGetSymbolAddress((void**)&ECS,    g_ECS);
  cudaGetSymbolAddress((void**)&ecsb,   g_ecsb);
  cudaGetSymbolAddress((void**)&Wg,     g_Wg);
  cudaGetSymbolAddress((void**)&uv,     g_u);
  cudaGetSymbolAddress((void**)&vv,     g_v);

  const int M = MROWS_;

  init_tables_k<<<1,256>>>(c256, s256, win, invwin, dstat);
  ecs_k<<<ECSN_,256>>>(enc_w, enc_b, c256, s256, win, ECS, ecsb);
  pack_k<<<KPACK_,256>>>(dec_w, dec_b, c256, s256, invwin, Bpack, biasPack);
  prep_wg_k<<<NBLK_*HH_*BTL_/4/256,256>>>(c2w, g2g, Wg);
  prep_uv_k<<<dim3(NBLK_,2),512>>>(c2w, g2g, g2b, uv, vv);
  frames_k<<<M,256>>>(audios, frames);

  // fused encoder + spectrum: frames @ ECS (N=528; relu on cols<256)
  gemmT<4,false><<<dim3(5,63),256>>>(frames, ECS, ecsb, ecs, M, ECSN_, 256, 256,
                                     nullptr, nullptr, nullptr, nullptr, nullptr);
  cln_k<<<M,128>>>(ecs, bgam, bbet, xc);
  // bottleneck (K=385, lda=400 zero-padded)
  gemmT<0,false><<<dim3(2,63),256>>>(xc, bw, bbi, x, M, 256, 385, FCP_,
                                     nullptr, nullptr, nullptr, nullptr, nullptr);

  // persistent TCN: all 32 blocks, one launch, software grid barriers
  tcn_k<<<TCNB_,256>>>(x, y1, y2, c1w, c1b, p1, dwv, g1g, g1b, p2,
                       Wg, c2b, uv, vv, dstat);

  // separator: x @ sep_w + sep_b (N=7700)
  gemmT<0,false><<<dim3(61,63),256>>>(x, sw, sb, emb, M, NSEP_, 256, 256,
                                      nullptr, nullptr, nullptr, nullptr, nullptr);
  attr_part_k<<<NB_*NPAIR_*ANS_,128>>>(emb, anchors, apart);
  attr_comb_k<<<NB_*NPAIR_,64>>>(apart, attrAll, sp01);
  choose_k<<<1,32>>>(sp01, attrAll, attv);
  code_k<<<M,128>>>(emb, attv, ecs, rows);
  // fused conv-decode + iSTFT GEMM (K=514, lda=528 zero-padded)
  gemmT<0,false><<<dim3(2,125),256>>>(rows, Bpack, biasPack, tot, MROWS2_, 256, 514, KPACKP_,
                                      nullptr, nullptr, nullptr, nullptr, nullptr);
  ola_k<<<(NB_*2*LAUD_+255)/256,256>>>(tot, out);
}

// round 17
// speedup vs baseline: 1.0764x; 1.0764x over previous
#include <cuda_runtime.h>
#include <math.h>
#include <float.h>

// ---------------- problem constants ----------------
#define NB_    8
#define TT_    497
#define LAUD_  32000
#define HOP_   64
#define NFFT_  256
#define AE_    256
#define BTL_   256
#define HH_    512
#define FC_    385
#define FCP_   400        // padded stride for xc (K=385 -> 25*16)
#define NFREQ_ 129
#define EMBD_  20
#define NBLK_  32
#define NPAIR_ 15
#define KPACK_ 514
#define KPACKP_ 528       // padded stride for rows (33*16)
#define ECSN_  528        // fused enc+spec row: [0,256) enc, [256,385) Re, [392,521) Im
#define RE0_   256
#define IM0_   392
#define ANS_   64
#define MROWS_ (NB_*TT_)          // 3976
#define MROWS2_ (NB_*2*TT_)       // 7952
#define NSEP_  (FC_*EMBD_)        // 7700

// ---------------- device scratch ----------------
__device__ float g_ecs[(long)MROWS_*ECSN_];
__device__ float g_xc[MROWS_*FCP_];
__device__ float g_x[MROWS_*BTL_];
__device__ float g_y1[MROWS_*HH_];
__device__ float g_y2[MROWS_*HH_];
__device__ float g_emb[(long)MROWS_*NSEP_];
__device__ float g_rows[(long)MROWS2_*KPACKP_];
__device__ float g_tot[MROWS2_*NFFT_];
// per-iteration gLN accumulators: slot = 2*i (y1 stats) or 2*i+1 (y2 stats)
__device__ double g_dstat[NBLK_*2*16];
__device__ float g_apart[NB_*NPAIR_*ANS_*42];
__device__ float g_attrAll[NB_*NPAIR_*40];
__device__ float g_sp01[NB_*NPAIR_];
__device__ float g_att[NB_*40];
__device__ float g_c256[256], g_s256[256], g_win[256], g_invwin[256];
__device__ float g_Bpack[KPACK_*256], g_biasPack[256];
__device__ float g_ECS[NFFT_*ECSN_];
__device__ float g_ecsb[ECSN_];
__device__ float g_Wg[NBLK_*HH_*BTL_];
__device__ float g_u[NBLK_*BTL_], g_v[NBLK_*BTL_];

__constant__ int d_combs[NPAIR_][2] = {
  {0,1},{0,2},{0,3},{0,4},{0,5},{1,2},{1,3},{1,4},{1,5},
  {2,3},{2,4},{2,5},{3,4},{3,5},{4,5}
};

// ---------------- tables (also zeroes stat accumulators) ----------------
__global__ void init_tables_k(float* c, float* s, float* win, float* invwin,
                              double* dstat) {
  int n = threadIdx.x;
  double a = 2.0 * 3.14159265358979323846 * (double)n / 256.0;
  double cv = cos(a), sv = sin(a);
  c[n] = (float)cv; s[n] = (float)sv;
  float w = (float)sqrt(0.5 - 0.5 * cv);
  win[n] = w;
  #pragma unroll
  for (int q = 0; q < 4; q++) dstat[n + q*256] = 0.0;
  __syncthreads();
  __shared__ float dn[64];
  if (n < 64) {
    float d = 0.f;
    for (int q = 0; q < 4; q++) { float wv = win[n + 64*q]; d += wv*wv; }
    dn[n] = d;
  }
  __syncthreads();
  invwin[n] = win[n] / dn[n & 63];
}

// fused encoder + windowed-DFT matrix:
// ECS[k][j] = enc_w[k][j]                (j < 256)
//           = win[k]*cos(2pi*k*jj/256)   (j = 256+jj, jj < 129)
//           = -win[k]*sin(2pi*k*jj/256)  (j = 392+jj, jj < 129)
//           = 0 otherwise
__global__ void ecs_k(const float* __restrict__ enc_w, const float* __restrict__ enc_b,
                      const float* __restrict__ c, const float* __restrict__ s,
                      const float* __restrict__ win,
                      float* __restrict__ ECS, float* __restrict__ ecsb) {
  int j = blockIdx.x, n = threadIdx.x;
  float v;
  if (j < 256) v = enc_w[n*256 + j];
  else {
    int jj = j - RE0_;
    if (jj < NFREQ_) v = win[n] * c[(n * jj) & 255];
    else if (j >= IM0_ && j < IM0_ + NFREQ_) v = -win[n] * s[(n * (j - IM0_)) & 255];
    else v = 0.f;
  }
  ECS[n * ECSN_ + j] = v;
  if (n == 0) ecsb[j] = (j < 256) ? enc_b[j] : 0.f;
}

__global__ void pack_k(const float* __restrict__ dec_w, const float* __restrict__ dec_b,
                       const float* __restrict__ c, const float* __restrict__ s,
                       const float* __restrict__ invwin,
                       float* __restrict__ Bp, float* __restrict__ biasP) {
  int k = blockIdx.x, n = threadIdx.x;
  float v;
  if (k < 256) {
    v = 0.5f * dec_w[k*256 + n];
  } else if (k < 385) {
    int j = k - 256;
    float wj = (j == 0 || j == 128) ? 1.f : 2.f;
    int m = (j * n) & 255;
    v = 0.5f * invwin[n] * wj * c[m] * (1.f/256.f);
  } else {
    int j = k - 385;
    float wj = (j == 0 || j == 128) ? 1.f : 2.f;
    int m = (j * n) & 255;
    v = -0.5f * invwin[n] * wj * s[m] * (1.f/256.f);
  }
  Bp[k*256 + n] = v;
  if (k == 0) biasP[n] = 0.5f * dec_b[n];
}

// Wg = g2g (k-wise) * c2w — fully parallel elementwise (float4)
__global__ void prep_wg_k(const float* __restrict__ c2w, const float* __restrict__ g2g,
                          float* __restrict__ Wg) {
  long idx = (long)blockIdx.x * 256 + threadIdx.x;
  int i = (int)(idx / (HH_*BTL_/4));
  int rem = (int)(idx % (HH_*BTL_/4));
  int k = rem / (BTL_/4);
  float gv = g2g[i*HH_ + k];
  float4 w = ((const float4*)c2w)[idx];
  w.x *= gv; w.y *= gv; w.z *= gv; w.w *= gv;
  ((float4*)Wg)[idx] = w;
}

__global__ __launch_bounds__(512)
void prep_uv_k(const float* __restrict__ c2w, const float* __restrict__ g2g,
               const float* __restrict__ g2b,
               float* __restrict__ u, float* __restrict__ v) {
  int i = blockIdx.x;
  int l = threadIdx.x & 127;
  int n = blockIdx.y * 128 + l;
  int ks = threadIdx.x >> 7;
  const float* W  = c2w + (long)i*HH_*BTL_ + n;
  const float* gg = g2g + i*HH_;
  const float* bb = g2b + i*HH_;
  float au = 0.f, av = 0.f;
  int k0 = ks * 128;
  #pragma unroll 4
  for (int k = k0; k < k0 + 128; k++) {
    float w = W[(long)k*BTL_];
    au = fmaf(bb[k], w, au);
    av = fmaf(gg[k], w, av);
  }
  __shared__ float su[4][128], sv[4][128];
  su[ks][l] = au; sv[ks][l] = av;
  __syncthreads();
  if (ks == 0) {
    u[i*BTL_ + n] = (su[0][l] + su[1][l]) + (su[2][l] + su[3][l]);
    v[i*BTL_ + n] = (sv[0][l] + sv[1][l]) + (sv[2][l] + sv[3][l]);
  }
}

// ---------------- cLN (reads fused ecs buffer) ----------------
__global__ void cln_k(const float* __restrict__ ecs,
                      const float* __restrict__ gamma, const float* __restrict__ beta,
                      float* __restrict__ xc) {
  int bt = blockIdx.x, tid = threadIdx.x;
  const float* row = ecs + (long)bt * ECSN_;
  __shared__ float vals[FC_];
  for (int f = tid; f < FC_; f += 128) {
    if (f < AE_) vals[f] = row[f];
    else {
      int j = f - AE_;
      float re = row[RE0_ + j];
      float im = row[IM0_ + j];
      vals[f] = log1pf(sqrtf(re*re + im*im));
    }
  }
  __syncthreads();
  double s = 0.0, ss = 0.0;
  for (int f = tid; f < FC_; f += 128) { double v = vals[f]; s += v; ss += v*v; }
  __shared__ double rs[128], rss[128];
  rs[tid] = s; rss[tid] = ss; __syncthreads();
  for (int o = 64; o > 0; o >>= 1) {
    if (tid < o) { rs[tid] += rs[tid+o]; rss[tid] += rss[tid+o]; }
    __syncthreads();
  }
  __shared__ float mS, iS;
  if (tid == 0) {
    double m = rs[0] / FC_;
    double var = rss[0] / FC_ - m*m;
    mS = (float)m; iS = (float)rsqrt(var + 1e-12);
  }
  __syncthreads();
  for (int f = tid; f < FC_; f += 128)
    xc[bt*FCP_ + f] = (vals[f] - mS) * iS * gamma[f] + beta[f];
  for (int f = FC_ + tid; f < FCP_; f += 128)
    xc[bt*FCP_ + f] = 0.f;
}

// ---------------- tf32 helpers ----------------
__device__ __forceinline__ void split_tf32(float x, unsigned& h, unsigned& l) {
  asm("cvt.rna.tf32.f32 %0, %1;" : "=r"(h) : "f"(x));
  float r = x - __uint_as_float(h);
  asm("cvt.rna.tf32.f32 %0, %1;" : "=r"(l) : "f"(r));
}

__device__ __forceinline__ void mma8(float* c, const unsigned* a, const unsigned* b) {
  asm volatile(
    "mma.sync.aligned.m16n8k8.row.col.f32.tf32.tf32.f32 "
    "{%0,%1,%2,%3}, {%4,%5,%6,%7}, {%8,%9}, {%0,%1,%2,%3};\n"
    : "+f"(c[0]), "+f"(c[1]), "+f"(c[2]), "+f"(c[3])
    : "r"(a[0]), "r"(a[1]), "r"(a[2]), "r"(a[3]), "r"(b[0]), "r"(b[1]));
}

__device__ __forceinline__ float wsum(float x) {
  #pragma unroll
  for (int o = 16; o > 0; o >>= 1) x += __shfl_down_sync(0xffffffffu, x, o);
  return x;
}

// ---------------- tf32 tensor-core GEMM (R14-winning config) ----------------
// Block 64x128x16, 256 threads = 8 warps (2M x 4N), warp tile 32x32.
// Raw fp32 in XOR-swizzled smem; split to tf32 hi/lo at fragment-load time;
// 3xTF32 compensation. EPI: 0 none, 1 relu, 2 prelu, 3 residual+gLN affine,
// 4 relu-on-cols<256 with A computed on-the-fly from stereo audio frames
//   (A[bt][k] = aud[b*2L + t*HOP + k] + aud[... + L]).
// STAT: fused per-batch (sum,sumsq) accumulation into dstat.
template<int EPI, bool STAT>
__global__ __launch_bounds__(256)
void gemmT(const float* __restrict__ A, const float* __restrict__ Bm,
           const float* __restrict__ bias, float* __restrict__ C,
           int M, int N, int K, int lda,
           const float* __restrict__ prelu,
           const float* __restrict__ uvec, const float* __restrict__ vvec,
           const double* __restrict__ part, double* __restrict__ dstat) {
  constexpr int BM = 64, BN = 128, BK = 16;
  __shared__ float As[2][BM][BK];    // col k ^ (4*((m>>1)&3))
  __shared__ float Bs[2][BK][BN];    // col n ^ (8*(k&3))
  __shared__ float s_m[8], s_i[8];
  __shared__ double wred[8][4];

  const int tid = threadIdx.x;
  if (EPI == 3 && tid < 8) {
    const double pb = (double)(TT_*HH_);
    double mm = part[tid*2] / pb;
    s_m[tid] = (float)mm;
    s_i[tid] = (float)rsqrt(part[tid*2+1] / pb - mm*mm + 1e-12);
  }

  const int row0 = blockIdx.y * BM, col0 = blockIdx.x * BN;
  const int wid = tid >> 5, lane = tid & 31;
  const int g = lane >> 2, t = lane & 3;
  const int m0w = (wid >> 2) * 32;
  const int n0w = (wid & 3) * 32;

  float acc[2][4][4];
  #pragma unroll
  for (int i = 0; i < 2; i++)
    #pragma unroll
    for (int j = 0; j < 4; j++)
      #pragma unroll
      for (int q = 0; q < 4; q++) acc[i][j][q] = 0.f;

  float4 aR, bR[2];
  const int am = tid >> 2, ak4 = (tid & 3) << 2;
  const int asw = ak4 ^ (4 * ((am >> 1) & 3));

  auto loadA = [&](int kt) {
    int row = row0 + am, gk = kt * BK + ak4;
    float4 r = make_float4(0.f, 0.f, 0.f, 0.f);
    if (row < M) {
      if (EPI == 4) {
        // on-the-fly framing from stereo audio (A = audios)
        int b = row / TT_, tt = row % TT_;
        long off = (long)b * 2 * LAUD_ + tt * HOP_ + gk;
        float4 a0 = *(const float4*)(A + off);
        float4 a1 = *(const float4*)(A + off + LAUD_);
        r = make_float4(a0.x + a1.x, a0.y + a1.y, a0.z + a1.z, a0.w + a1.w);
      } else {
        r = *(const float4*)(A + (long)row * lda + gk);
      }
    }
    aR = r;
  };
  auto loadB = [&](int kt) {
    #pragma unroll
    for (int p = 0; p < 2; p++) {
      int idx = tid + p * 256;
      int bk = idx >> 5, bn4 = (idx & 31) << 2;
      int gk = kt * BK + bk, col = col0 + bn4;
      float4 r = make_float4(0.f, 0.f, 0.f, 0.f);
      if (gk < K) {
        const float* bp = Bm + (long)gk * N + col;
        if (col + 3 < N) r = *(const float4*)bp;
        else {
          if (col     < N) r.x = bp[0];
          if (col + 1 < N) r.y = bp[1];
          if (col + 2 < N) r.z = bp[2];
        }
      }
      bR[p] = r;
    }
  };
  auto storeT = [&](int buf) {
    *(float4*)&As[buf][am][asw] = aR;
    #pragma unroll
    for (int p = 0; p < 2; p++) {
      int idx = tid + p * 256;
      int bk = idx >> 5, bn4 = (idx & 31) << 2;
      *(float4*)&Bs[buf][bk][bn4 ^ (8 * (bk & 3))] = bR[p];
    }
  };

  const int ktot = (K + BK - 1) / BK;
  loadA(0); loadB(0);
  storeT(0);
  __syncthreads();

  for (int kt = 0; kt < ktot; kt++) {
    const int buf = kt & 1;
    const bool more = (kt + 1 < ktot);
    if (more) { loadA(kt + 1); loadB(kt + 1); }

    #pragma unroll
    for (int ks = 0; ks < 2; ks++) {
      const int k1 = ks * 8 + t, k2 = k1 + 4;
      unsigned ah[2][4], al[2][4];
      #pragma unroll
      for (int mi = 0; mi < 2; mi++) {
        int rA = m0w + mi * 16 + g;
        int sw = 4 * ((rA >> 1) & 3);
        float r0 = As[buf][rA    ][k1 ^ sw];
        float r1 = As[buf][rA + 8][k1 ^ sw];
        float r2 = As[buf][rA    ][k2 ^ sw];
        float r3 = As[buf][rA + 8][k2 ^ sw];
        split_tf32(r0, ah[mi][0], al[mi][0]);
        split_tf32(r1, ah[mi][1], al[mi][1]);
        split_tf32(r2, ah[mi][2], al[mi][2]);
        split_tf32(r3, ah[mi][3], al[mi][3]);
      }
      unsigned bh[4][2], bl[4][2];
      const int bsw = 8 * (k1 & 3);
      #pragma unroll
      for (int ni = 0; ni < 4; ni++) {
        int cn = (n0w + ni * 8 + g) ^ bsw;
        float r0 = Bs[buf][k1][cn];
        float r1 = Bs[buf][k2][cn];
        split_tf32(r0, bh[ni][0], bl[ni][0]);
        split_tf32(r1, bh[ni][1], bl[ni][1]);
      }
      #pragma unroll
      for (int mi = 0; mi < 2; mi++)
        #pragma unroll
        for (int ni = 0; ni < 4; ni++) {
          mma8(acc[mi][ni], ah[mi], bl[ni]);
          mma8(acc[mi][ni], al[mi], bh[ni]);
          mma8(acc[mi][ni], ah[mi], bh[ni]);
        }
    }

    if (more) { storeT(buf ^ 1); __syncthreads(); }
  }

  // epilogue
  const int bLo = row0 / TT_;
  const int rsplit = (bLo + 1) * TT_;
  float sLo = 0.f, qLo = 0.f, sHi = 0.f, qHi = 0.f;
  #pragma unroll
  for (int mi = 0; mi < 2; mi++) {
    #pragma unroll
    for (int ii = 0; ii < 2; ii++) {
      int row = row0 + m0w + mi * 16 + g + ii * 8;
      if (row >= M) continue;
      float si = 1.f, smn = 0.f;
      if (EPI == 3) { int b = row / TT_; si = s_i[b]; smn = s_m[b]; }
      float* crow = C + (long)row * N;
      float rs = 0.f, rq = 0.f;
      #pragma unroll
      for (int ni = 0; ni < 4; ni++) {
        #pragma unroll
        for (int jj = 0; jj < 2; jj++) {
          int cc = col0 + n0w + ni * 8 + 2 * t + jj;
          if (cc >= N) continue;
          float vx = acc[mi][ni][ii * 2 + jj];
          if (EPI == 0) vx += bias[cc];
          if (EPI == 1) { vx += bias[cc]; vx = fmaxf(vx, 0.f); }
          if (EPI == 2) { vx += bias[cc]; vx = fmaxf(vx, 0.f) + prelu[cc] * fminf(vx, 0.f); }
          if (EPI == 3) vx = crow[cc] + si * vx + (uvec[cc] - smn * si * vvec[cc]) + bias[cc];
          if (EPI == 4) { vx += bias[cc]; if (cc < 256) vx = fmaxf(vx, 0.f); }
          crow[cc] = vx;
          if (STAT) { rs += vx; rq = fmaf(vx, vx, rq); }
        }
      }
      if (STAT) {
        if (row < rsplit) { sLo += rs; qLo += rq; }
        else              { sHi += rs; qHi += rq; }
      }
    }
  }
  if (STAT) {
    sLo = wsum(sLo); qLo = wsum(qLo); sHi = wsum(sHi); qHi = wsum(qHi);
    if (lane == 0) {
      wred[wid][0] = sLo; wred[wid][1] = qLo;
      wred[wid][2] = sHi; wred[wid][3] = qHi;
    }
    __syncthreads();
    if (tid < 4) {
      double a = 0.0;
      #pragma unroll
      for (int w = 0; w < 8; w++) a += wred[w][tid];
      int b = (tid < 2) ? bLo : bLo + 1;
      if (b < NB_ && a != 0.0) atomicAdd(&dstat[b*2 + (tid & 1)], a);
    }
  }
}

// ---------------- dwconv (fused y1-stat finalize + gLN + conv + prelu + y2-stat) ----
__global__ __launch_bounds__(256)
void dwconv2_k(const float* __restrict__ y1, float* __restrict__ y2,
               const float* __restrict__ w, const double* __restrict__ partA,
               double* __restrict__ dstatB,
               const float* __restrict__ g, const float* __restrict__ be,
               const float* __restrict__ p2, int d) {
  __shared__ float s_m[8], s_i[8];
  __shared__ double wred[8][2];
  __shared__ double wredH[8][2];
  int tid = threadIdx.x;
  if (tid < 8) {
    const double pb = (double)(TT_*HH_);
    double mm = partA[tid*2] / pb;
    s_m[tid] = (float)mm;
    s_i[tid] = (float)rsqrt(partA[tid*2+1] / pb - mm*mm + 1e-12);
  }
  __syncthreads();
  int idx4 = blockIdx.x * 256 + tid;
  int c4 = (idx4 & 127) << 2;
  int bt = idx4 >> 7;
  int t = bt % TT_, b = bt / TT_;
  float m = s_m[b], si = s_i[b];
  float4 gg = *(const float4*)(g + c4);
  float4 bb = *(const float4*)(be + c4);
  float4 pp = *(const float4*)(p2 + c4);
  float4 acc = make_float4(0.f,0.f,0.f,0.f);
  #pragma unroll
  for (int k = 0; k < 3; k++) {
    int tt = t + (k - 1) * d;
    if (tt >= 0 && tt < TT_) {
      float4 v = *(const float4*)(y1 + ((long)(b*TT_ + tt))*HH_ + c4);
      float4 wv = *(const float4*)(w + k*HH_ + c4);
      acc.x = fmaf(wv.x, (v.x - m)*si*gg.x + bb.x, acc.x);
      acc.y = fmaf(wv.y, (v.y - m)*si*gg.y + bb.y, acc.y);
      acc.z = fmaf(wv.z, (v.z - m)*si*gg.z + bb.z, acc.z);
      acc.w = fmaf(wv.w, (v.w - m)*si*gg.w + bb.w, acc.w);
    }
  }
  float4 o;
  o.x = fmaxf(acc.x, 0.f) + pp.x * fminf(acc.x, 0.f);
  o.y = fmaxf(acc.y, 0.f) + pp.y * fminf(acc.y, 0.f);
  o.z = fmaxf(acc.z, 0.f) + pp.z * fminf(acc.z, 0.f);
  o.w = fmaxf(acc.w, 0.f) + pp.w * fminf(acc.w, 0.f);
  *(float4*)(y2 + (long)idx4*4) = o;

  const int bLo = (blockIdx.x * 2) / TT_;
  float s = o.x + o.y + o.z + o.w;
  float q = o.x*o.x + o.y*o.y + o.z*o.z + o.w*o.w;
  float sLo = (b == bLo) ? s : 0.f, qLo = (b == bLo) ? q : 0.f;
  float sHi = (b == bLo) ? 0.f : s, qHi = (b == bLo) ? 0.f : q;
  sLo = wsum(sLo); qLo = wsum(qLo); sHi = wsum(sHi); qHi = wsum(qHi);
  int lane = tid & 31, wid = tid >> 5;
  if (lane == 0) {
    wred[wid][0] = sLo; wred[wid][1] = qLo;
    wredH[wid][0] = sHi; wredH[wid][1] = qHi;
  }
  __syncthreads();
  if (tid < 2) {
    double a = 0.0, ah = 0.0;
    #pragma unroll
    for (int w2 = 0; w2 < 8; w2++) { a += wred[w2][tid]; ah += wredH[w2][tid]; }
    if (a  != 0.0) atomicAdd(&dstatB[bLo*2 + tid], a);
    int bH = bLo + 1;
    if (bH < NB_ && ah != 0.0) atomicAdd(&dstatB[bH*2 + tid], ah);
  }
}

// ---------------- attractor ----------------
__global__ __launch_bounds__(128)
void attr_part_k(const float* __restrict__ emb, const float* __restrict__ anchors,
                 float* __restrict__ part) {
  int bp = blockIdx.x % (NB_*NPAIR_);
  int s  = blockIdx.x / (NB_*NPAIR_);
  int b = bp / NPAIR_, p = bp % NPAIR_;
  int tid = threadIdx.x;
  __shared__ float a0[EMBD_], a1[EMBD_];
  if (tid < EMBD_) {
    a0[tid] = anchors[d_combs[p][0] * EMBD_ + tid];
    a1[tid] = anchors[d_combs[p][1] * EMBD_ + tid];
  }
  __syncthreads();
  const int rows = TT_ * FC_;
  int chunk = (rows + ANS_ - 1) / ANS_;
  int st = s * chunk, en = min(rows, st + chunk);
  float num0[EMBD_], sev[EMBD_];
  #pragma unroll
  for (int i = 0; i < EMBD_; i++) { num0[i] = 0.f; sev[i] = 0.f; }
  float den0 = 0.f;
  const float* base = emb + (long)b * rows * EMBD_;
  for (int r = st + tid; r < en; r += 128) {
    const float4* e4 = (const float4*)(base + (long)r * EMBD_);
    float ev[EMBD_];
    #pragma unroll
    for (int q = 0; q < 5; q++) {
      float4 v = e4[q];
      ev[q*4+0] = v.x; ev[q*4+1] = v.y; ev[q*4+2] = v.z; ev[q*4+3] = v.w;
    }
    float dd0 = 0.f, dd1 = 0.f;
    #pragma unroll
    for (int i = 0; i < EMBD_; i++) { dd0 = fmaf(ev[i], a0[i], dd0); dd1 = fmaf(ev[i], a1[i], dd1); }
    float s0 = 1.f / (1.f + expf(dd1 - dd0));
    den0 += s0;
    #pragma unroll
    for (int i = 0; i < EMBD_; i++) { num0[i] = fmaf(s0, ev[i], num0[i]); sev[i] += ev[i]; }
  }
  __shared__ float red[4][41];
  int lane = tid & 31, w = tid >> 5;
  den0 = wsum(den0);
  #pragma unroll
  for (int i = 0; i < EMBD_; i++) { num0[i] = wsum(num0[i]); sev[i] = wsum(sev[i]); }
  if (lane == 0) {
    red[w][0] = den0;
    #pragma unroll
    for (int i = 0; i < EMBD_; i++) { red[w][1+i] = num0[i]; red[w][21+i] = sev[i]; }
  }
  __syncthreads();
  if (tid < 41) {
    float a = red[0][tid] + red[1][tid] + red[2][tid] + red[3][tid];
    part[(bp * ANS_ + s) * 42 + tid] = a;
  }
}

__global__ void attr_comb_k(const float* __restrict__ part, float* __restrict__ attrAll,
                            float* __restrict__ sp01) {
  int bp = blockIdx.x, tid = threadIdx.x;
  __shared__ float comb[41];
  if (tid < 41) {
    double a = 0.0;
    for (int s = 0; s < ANS_; s++) a += part[(bp * ANS_ + s) * 42 + tid];
    comb[tid] = (float)a;
  }
  __syncthreads();
  __shared__ float at[40];
  if (tid < 40) {
    int c = tid / EMBD_, e = tid % EMBD_;
    float den0 = comb[0];
    float den1 = (float)(TT_ * FC_) - den0;
    float val;
    if (c == 0) val = comb[1 + e] / den0;
    else        val = (comb[21 + e] - comb[1 + e]) / den1;
    at[tid] = val;
    attrAll[bp * 40 + tid] = val;
  }
  __syncthreads();
  if (tid == 0) {
    float s = 0.f;
    for (int e = 0; e < EMBD_; e++) s += at[e] * at[EMBD_ + e];
    sp01[bp] = s;
  }
}

__global__ void choose_k(const float* __restrict__ sp01, const float* __restrict__ attrAll,
                         float* __restrict__ attract) {
  int b = threadIdx.x;
  if (b >= NB_) return;
  float best = sp01[b * NPAIR_];
  int bi = 0;
  for (int p = 1; p < NPAIR_; p++) {
    float v = sp01[b * NPAIR_ + p];
    if (v < best) { best = v; bi = p; }
  }
  for (int k = 0; k < 40; k++)
    attract[b * 40 + k] = attrAll[(b * NPAIR_ + bi) * 40 + k];
}

// ---------------- code rows ----------------
__global__ __launch_bounds__(128)
void code_k(const float* __restrict__ emb, const float* __restrict__ attract,
            const float* __restrict__ ecs, float* __restrict__ rows) {
  int bt = blockIdx.x, tid = threadIdx.x;
  int b = bt / TT_, t = bt % TT_;
  __shared__ float at[40];
  if (tid < 40) at[tid] = attract[b * 40 + tid];
  __syncthreads();
  const float* erow = ecs + (long)bt * ECSN_;
  long r0 = ((long)(b * 2 + 0) * TT_ + t) * KPACKP_;
  long r1 = ((long)(b * 2 + 1) * TT_ + t) * KPACKP_;
  for (int f = tid; f < FC_; f += 128) {
    const float4* e4 = (const float4*)(emb + ((long)bt * FC_ + f) * EMBD_);
    float l0 = 0.f, l1 = 0.f;
    #pragma unroll
    for (int q = 0; q < 5; q++) {
      float4 v = e4[q];
      l0 = fmaf(v.x, at[q*4+0], l0); l0 = fmaf(v.y, at[q*4+1], l0);
      l0 = fmaf(v.z, at[q*4+2], l0); l0 = fmaf(v.w, at[q*4+3], l0);
      l1 = fmaf(v.x, at[20+q*4+0], l1); l1 = fmaf(v.y, at[20+q*4+1], l1);
      l1 = fmaf(v.z, at[20+q*4+2], l1); l1 = fmaf(v.w, at[20+q*4+3], l1);
    }
    if (f < AE_) {
      float fe = erow[f];
      rows[r0 + f] = l0 * fe;
      rows[r1 + f] = l1 * fe;
    } else {
      int j = f - AE_;
      float re = erow[RE0_ + j];
      float im = erow[IM0_ + j];
      rows[r0 + 256 + j] = l0 * re;
      rows[r0 + 385 + j] = l0 * im;
      rows[r1 + 256 + j] = l1 * re;
      rows[r1 + 385 + j] = l1 * im;
    }
  }
  if (tid < KPACKP_ - KPACK_) {
    rows[r0 + KPACK_ + tid] = 0.f;
    rows[r1 + KPACK_ + tid] = 0.f;
  }
}

// ---------------- overlap-add ----------------
__global__ void ola_k(const float* __restrict__ tot, float* __restrict__ out) {
  int idx = blockIdx.x * blockDim.x + threadIdx.x;
  if (idx >= NB_ * 2 * LAUD_) return;
  int l = idx % LAUD_;
  int bc = idx / LAUD_;
  int tlo = (l >= NFFT_) ? ((l - NFFT_) >> 6) + 1 : 0;
  int thi = min(TT_ - 1, l >> 6);
  float acc = 0.f;
  for (int t = tlo; t <= thi; t++)
    acc += tot[((long)bc * TT_ + t) * NFFT_ + (l - (t << 6))];
  out[idx] = acc;
}

// ---------------- host orchestration ----------------
extern "C" void kernel_launch(void* const* d_in, const int* in_sizes, int n_in,
                              void* d_out, int out_size) {
  const float* audios = (const float*)d_in[0];
  const float* enc_w  = (const float*)d_in[1];
  const float* enc_b  = (const float*)d_in[2];
  const float* bgam   = (const float*)d_in[3];
  const float* bbet   = (const float*)d_in[4];
  const float* bw     = (const float*)d_in[5];
  const float* bbi    = (const float*)d_in[6];
  const float* c1w    = (const float*)d_in[7];
  const float* c1b    = (const float*)d_in[8];
  const float* p1     = (const float*)d_in[9];
  const float* g1g    = (const float*)d_in[10];
  const float* g1b    = (const float*)d_in[11];
  const float* dwv    = (const float*)d_in[12];
  const float* p2     = (const float*)d_in[13];
  const float* g2g    = (const float*)d_in[14];
  const float* g2b    = (const float*)d_in[15];
  const float* c2w    = (const float*)d_in[16];
  const float* c2b    = (const float*)d_in[17];
  const float* sw     = (const float*)d_in[18];
  const float* sb     = (const float*)d_in[19];
  const float* anchors= (const float*)d_in[20];
  const float* dec_w  = (const float*)d_in[21];
  const float* dec_b  = (const float*)d_in[22];
  float* out = (float*)d_out;

  float *ecs,*xc,*x,*y1,*y2,*emb,*rows,*tot;
  float *apart,*attrAll,*sp01,*attv;
  float *c256,*s256,*win,*invwin,*Bpack,*biasPack,*ECS,*ecsb,*Wg,*uv,*vv;
  double *dstat;
  cudaGetSymbolAddress((void**)&ecs,    g_ecs);
  cudaGetSymbolAddress((void**)&xc,     g_xc);
  cudaGetSymbolAddress((void**)&x,      g_x);
  cudaGetSymbolAddress((void**)&y1,     g_y1);
  cudaGetSymbolAddress((void**)&y2,     g_y2);
  cudaGetSymbolAddress((void**)&emb,    g_emb);
  cudaGetSymbolAddress((void**)&rows,   g_rows);
  cudaGetSymbolAddress((void**)&tot,    g_tot);
  cudaGetSymbolAddress((void**)&dstat,  g_dstat);
  cudaGetSymbolAddress((void**)&apart,  g_apart);
  cudaGetSymbolAddress((void**)&attrAll,g_attrAll);
  cudaGetSymbolAddress((void**)&sp01,   g_sp01);
  cudaGetSymbolAddress((void**)&attv,   g_att);
  cudaGetSymbolAddress((void**)&c256,   g_c256);
  cudaGetSymbolAddress((void**)&s256,   g_s256);
  cudaGetSymbolAddress((void**)&win,    g_win);
  cudaGetSymbolAddress((void**)&invwin, g_invwin);
  cudaGetSymbolAddress((void**)&Bpack,  g_Bpack);
  cudaGetSymbolAddress((void**)&biasPack, g_biasPack);
  cudaGetSymbolAddress((void**)&ECS,    g_ECS);
  cudaGetSymbolAddress((void**)&ecsb,   g_ecsb);
  cudaGetSymbolAddress((void**)&Wg,     g_Wg);
  cudaGetSymbolAddress((void**)&uv,     g_u);
  cudaGetSymbolAddress((void**)&vv,     g_v);

  const int M = MROWS_;

  init_tables_k<<<1,256>>>(c256, s256, win, invwin, dstat);
  ecs_k<<<ECSN_,256>>>(enc_w, enc_b, c256, s256, win, ECS, ecsb);
  pack_k<<<KPACK_,256>>>(dec_w, dec_b, c256, s256, invwin, Bpack, biasPack);
  prep_wg_k<<<NBLK_*HH_*BTL_/4/256,256>>>(c2w, g2g, Wg);
  prep_uv_k<<<dim3(NBLK_,2),512>>>(c2w, g2g, g2b, uv, vv);

  // fused framing + encoder + spectrum: A computed from audios on the fly
  gemmT<4,false><<<dim3(5,63),256>>>(audios, ECS, ecsb, ecs, M, ECSN_, 256, 0,
                                     nullptr, nullptr, nullptr, nullptr, nullptr);
  cln_k<<<M,128>>>(ecs, bgam, bbet, xc);
  // bottleneck (K=385, lda=400 zero-padded)
  gemmT<0,false><<<dim3(2,63),256>>>(xc, bw, bbi, x, M, 256, 385, FCP_,
                                     nullptr, nullptr, nullptr, nullptr, nullptr);

  for (int i = 0; i < NBLK_; i++) {
    int di = 1 << (i & 7);
    double* dA = dstat + (2*i) * 16;
    double* dB = dstat + (2*i + 1) * 16;
    // c1 GEMM + prelu + fused y1-stat accumulation
    gemmT<2,true><<<dim3(4,63),256>>>(x, c1w + (long)i*BTL_*HH_, c1b + i*HH_, y1,
                                      M, 512, 256, 256, p1 + i*HH_,
                                      nullptr, nullptr, nullptr, dA);
    // gLN1 finalize + dwconv + prelu2 + fused y2-stat accumulation
    dwconv2_k<<<MROWS_*HH_/4/256,256>>>(y1, y2, dwv + i*3*HH_, dA, dB,
                                        g1g + i*HH_, g1b + i*HH_, p2 + i*HH_, di);
    // c2 GEMM with gLN2 finalize in epilogue + residual add
    gemmT<3,false><<<dim3(2,63),256>>>(y2, Wg + (long)i*HH_*BTL_, c2b + i*BTL_, x,
                                       M, 256, 512, 512, nullptr,
                                       uv + i*BTL_, vv + i*BTL_, dB, nullptr);
  }

  // separator: x @ sep_w + sep_b (N=7700)
  gemmT<0,false><<<dim3(61,63),256>>>(x, sw, sb, emb, M, NSEP_, 256, 256,
                                      nullptr, nullptr, nullptr, nullptr, nullptr);
  attr_part_k<<<NB_*NPAIR_*ANS_,128>>>(emb, anchors, apart);
  attr_comb_k<<<NB_*NPAIR_,64>>>(apart, attrAll, sp01);
  choose_k<<<1,32>>>(sp01, attrAll, attv);
  code_k<<<M,128>>>(emb, attv, ecs, rows);
  // fused conv-decode + iSTFT GEMM (K=514, lda=528 zero-padded)
  gemmT<0,false><<<dim3(2,125),256>>>(rows, Bpack, biasPack, tot, MROWS2_, 256, 514, KPACKP_,
                                      nullptr, nullptr, nullptr, nullptr, nullptr);
  ola_k<<<(NB_*2*LAUD_+255)/256,256>>>(tot, out);
}